// round 1
// baseline (speedup 1.0000x reference)
#include <cuda_runtime.h>

#define FULLMASK 0xffffffffu

constexpr int NND = 20000;
constexpr int DEG = 16;
constexpr int NQ  = 17;    // ego-graph size n = DEG+1
constexpr int TT  = 16;    // templates
constexpr int MM  = 8;     // template nodes
constexpr int DD  = 64;    // feature dim
constexpr int NODES_PER_BLK = 4;
constexpr int THREADS = 256;

// Work in base-2 units scaled by 1/EPS:  b = cost * log2(e)/EPS
constexpr float SIG       = 14.4269504088896340f;   // log2(e)/0.1
constexpr float LOGP2     = -4.0874628412503390f;   // log2(1/17)
constexpr float LOGQ2     = -3.0f;                  // log2(1/8)
constexpr float SCALEBACK = 0.0693147180559945f;    // EPS*ln(2)

__device__ __forceinline__ float ex2f_(float x) {
    float y; asm("ex2.approx.ftz.f32 %0, %1;" : "=f"(y) : "f"(x)); return y;
}
__device__ __forceinline__ float lg2f_(float x) {
    float y; asm("lg2.approx.f32 %0, %1;" : "=f"(y) : "f"(x)); return y;
}

// dynamic smem layout (floats):
//  [0, 8192)              tfT  : transposed template features [d][t*8+j]
//  [8192, 8192+4352)      floc : gathered ego features [4 nodes][17][64]
//  [+1024)                c2s  : template structure [16][8][8]
//  [+128)                 wcol : per-column constant 0.5*(|tf|^2 + b)
//  [+68)                  rrow : per-row constant 0.5*(|x|^2 + a)
__global__ __launch_bounds__(THREADS, 2)
void ltfgw_kernel(const float* __restrict__ x,
                  const int*   __restrict__ edge_dst,
                  const float* __restrict__ tf,
                  const float* __restrict__ tm,
                  float*       __restrict__ out)
{
    extern __shared__ float sm[];
    float* tfT  = sm;                    // 8192
    float* floc = sm + 8192;             // 4352
    float* c2s  = sm + 8192 + 4352;      // 1024
    float* wcol = c2s + 1024;            // 128
    float* rrow = wcol + 128;            // 68

    const int tid = threadIdx.x;
    const int node_base = blockIdx.x * NODES_PER_BLK;

    // ---- stage templates (transposed) ----
    for (int e = tid; e < TT * MM * DD; e += THREADS) {
        int d  = e & 63;
        int tj = e >> 6;                 // t*8 + j
        tfT[d * 128 + tj] = tf[e];
    }
    for (int e = tid; e < TT * MM * MM; e += THREADS)
        c2s[e] = tm[e];

    // ---- gather ego features: row 0 = node, rows 1..16 = neighbors ----
    for (int li = tid; li < NODES_PER_BLK * NQ * (DD / 4); li += THREADS) {
        int row = li >> 4;
        int q   = li & 15;
        int nl  = row / NQ;
        int i   = row - nl * NQ;
        int node = node_base + nl;
        int g = (i == 0) ? node : edge_dst[node * DEG + (i - 1)];
        reinterpret_cast<float4*>(floc)[row * 16 + q] =
            reinterpret_cast<const float4*>(x)[g * 16 + q];
    }
    __syncthreads();

    // ---- per-column constants: w = 0.5*(|tf_tj|^2 + (1/8)*sum_k C2[t,j,k]^2) ----
    if (tid < 128) {
        float sq = 0.f;
        #pragma unroll 8
        for (int d = 0; d < DD; d++) { float v = tfT[d * 128 + tid]; sq += v * v; }
        float bb = 0.f;
        #pragma unroll
        for (int k = 0; k < MM; k++) { float c = c2s[tid * 8 + k]; bb += c * c; }
        wcol[tid] = 0.5f * (sq + 0.125f * bb);
    } else if (tid < 128 + NODES_PER_BLK * NQ) {
        // per-row constants: r = 0.5*(|x_i|^2 + a_i), a_0 = 16/17, a_i = 1/17
        int rid = tid - 128;
        float sq = 0.f;
        #pragma unroll 8
        for (int d = 0; d < DD; d++) {
            float v = floc[rid * 64 + ((d + rid) & 63)];   // rotated: bank-conflict-free
            sq += v * v;
        }
        float a = ((rid % NQ) == 0) ? (16.f / 17.f) : (1.f / 17.f);
        rrow[rid] = 0.5f * (sq + a);
    }
    __syncthreads();

    // ---- lane mapping: 4 lanes per (node,template) pair, 2 columns per lane ----
    const int w    = tid >> 5, lane = tid & 31;
    const int nl   = w >> 1;
    const int grp  = lane >> 2, cl = lane & 3;
    const int t    = (w & 1) * 8 + grp;
    const int j0   = cl * 2;
    const int col0 = t * 8 + j0;

    // ---- feature cost (dot products), register-blocked over rows ----
    float b0[NQ], b1[NQ];
    #pragma unroll
    for (int i = 0; i < NQ; i++) { b0[i] = 0.f; b1[i] = 0.f; }

    const float* fl = floc + nl * NQ * DD;
    #pragma unroll 2
    for (int d4 = 0; d4 < DD; d4 += 4) {
        float2 t0 = *reinterpret_cast<const float2*>(&tfT[(d4 + 0) * 128 + col0]);
        float2 t1 = *reinterpret_cast<const float2*>(&tfT[(d4 + 1) * 128 + col0]);
        float2 t2 = *reinterpret_cast<const float2*>(&tfT[(d4 + 2) * 128 + col0]);
        float2 t3 = *reinterpret_cast<const float2*>(&tfT[(d4 + 3) * 128 + col0]);
        #pragma unroll
        for (int i = 0; i < NQ; i++) {
            float4 f4 = *reinterpret_cast<const float4*>(&fl[i * DD + d4]);  // broadcast
            b0[i] += f4.x * t0.x + f4.y * t1.x + f4.z * t2.x + f4.w * t3.x;
            b1[i] += f4.x * t0.y + f4.y * t1.y + f4.z * t2.y + f4.w * t3.y;
        }
    }
    // b = (r_i + w_j - dot) * SIG  == 0.5*(Mcost + constC)/EPS * log2(e)
    {
        const float w0 = wcol[col0], w1 = wcol[col0 + 1];
        #pragma unroll
        for (int i = 0; i < NQ; i++) {
            float r = rrow[nl * NQ + i];
            b0[i] = (r + w0 - b0[i]) * SIG;
            b1[i] = (r + w1 - b1[i]) * SIG;
        }
    }

    // C2 rows (symmetric => columns) for the H matvec
    float c2a[MM], c2b[MM];
    #pragma unroll
    for (int k = 0; k < MM; k++) {
        c2a[k] = c2s[(t * 8 + j0) * 8 + k];
        c2b[k] = c2s[(t * 8 + j0 + 1) * 8 + k];
    }
    // initial H from uniform plan G = 1/136:  s_k = 16/136, z_k = 1/136
    float cs0 = 0.f, cs1 = 0.f;
    #pragma unroll
    for (int k = 0; k < MM; k++) { cs0 += c2a[k]; cs1 += c2b[k]; }
    float ht0 = SIG * (16.f / 136.f) * cs0, hr0 = SIG * (1.f / 136.f) * cs0;
    float ht1 = SIG * (16.f / 136.f) * cs1, hr1 = SIG * (1.f / 136.f) * cs1;
    b0[0] -= ht0; b1[0] -= ht1;
    #pragma unroll
    for (int i = 1; i < NQ; i++) { b0[i] -= hr0; b1[i] -= hr1; }

    float F[NQ];
    float fgw = 0.f;

    #pragma unroll 1
    for (int outer = 0; outer < 4; outer++) {
        float G0 = 0.f, G1 = 0.f;
        #pragma unroll 1
        for (int it = 0; it < 10; it++) {
            // f-update: logsumexp over the 8 columns (4-lane butterfly)
            #pragma unroll
            for (int i = 0; i < NQ; i++) {
                float v0 = G0 - b0[i];
                float v1 = G1 - b1[i];
                float mx = fmaxf(v0, v1);
                mx = fmaxf(mx, __shfl_xor_sync(FULLMASK, mx, 1));
                mx = fmaxf(mx, __shfl_xor_sync(FULLMASK, mx, 2));
                float s = ex2f_(v0 - mx) + ex2f_(v1 - mx);
                s += __shfl_xor_sync(FULLMASK, s, 1);
                s += __shfl_xor_sync(FULLMASK, s, 2);
                F[i] = LOGP2 - (lg2f_(s) + mx);
            }
            // g-update: logsumexp over 17 rows, fully in-thread
            float m0a = F[0] - b0[0], m1a = F[0] - b1[0];
            float m0b = F[1] - b0[1], m1b = F[1] - b1[1];
            #pragma unroll
            for (int i = 2; i < NQ; i += 2) {
                m0a = fmaxf(m0a, F[i] - b0[i]);
                m1a = fmaxf(m1a, F[i] - b1[i]);
                if (i + 1 < NQ) {
                    m0b = fmaxf(m0b, F[i + 1] - b0[i + 1]);
                    m1b = fmaxf(m1b, F[i + 1] - b1[i + 1]);
                }
            }
            float m0 = fmaxf(m0a, m0b), m1 = fmaxf(m1a, m1b);
            float s0a = 0.f, s0b = 0.f, s1a = 0.f, s1b = 0.f;
            #pragma unroll
            for (int i = 0; i < NQ; i += 2) {
                s0a += ex2f_(F[i] - b0[i] - m0);
                s1a += ex2f_(F[i] - b1[i] - m1);
                if (i + 1 < NQ) {
                    s0b += ex2f_(F[i + 1] - b0[i + 1] - m0);
                    s1b += ex2f_(F[i + 1] - b1[i + 1] - m1);
                }
            }
            G0 = LOGQ2 - (lg2f_(s0a + s0b) + m0);
            G1 = LOGQ2 - (lg2f_(s1a + s1b) + m1);
        }

        // ---- transition: plan column sums z (row 0), s (rows 1..16), and G.b ----
        float z0, z1, s0 = 0.f, s1 = 0.f, gb0, gb1;
        {
            float g0v = ex2f_(F[0] + G0 - b0[0]);
            float g1v = ex2f_(F[0] + G1 - b1[0]);
            z0 = g0v; z1 = g1v;
            gb0 = g0v * b0[0]; gb1 = g1v * b1[0];
            #pragma unroll
            for (int i = 1; i < NQ; i++) {
                float a0 = ex2f_(F[i] + G0 - b0[i]);
                float a1 = ex2f_(F[i] + G1 - b1[i]);
                s0 += a0; s1 += a1;
                gb0 += a0 * b0[i]; gb1 += a1 * b1[i];
            }
        }
        // assemble full s[8], z[8] across the 4-lane group
        float sf[MM], zf[MM];
        const int lb = lane & ~3;
        #pragma unroll
        for (int kk = 0; kk < 4; kk++) {
            sf[2 * kk]     = __shfl_sync(FULLMASK, s0, lb + kk);
            sf[2 * kk + 1] = __shfl_sync(FULLMASK, s1, lb + kk);
            zf[2 * kk]     = __shfl_sync(FULLMASK, z0, lb + kk);
            zf[2 * kk + 1] = __shfl_sync(FULLMASK, z1, lb + kk);
        }
        // new H = (C1 G C2): row0 uses s.C2, rows>=1 use z.C2
        float ht0n = 0.f, hr0n = 0.f, ht1n = 0.f, hr1n = 0.f;
        #pragma unroll
        for (int k = 0; k < MM; k++) {
            ht0n += sf[k] * c2a[k]; hr0n += zf[k] * c2a[k];
            ht1n += sf[k] * c2b[k]; hr1n += zf[k] * c2b[k];
        }
        ht0n *= SIG; hr0n *= SIG; ht1n *= SIG; hr1n *= SIG;

        if (outer < 3) {
            // fold Δh into register-resident cost: b_new = b_old - (h_new - h_old)
            float dt0 = ht0n - ht0, dt1 = ht1n - ht1;
            float dr0 = hr0n - hr0, dr1 = hr1n - hr1;
            b0[0] -= dt0; b1[0] -= dt1;
            #pragma unroll
            for (int i = 1; i < NQ; i++) { b0[i] -= dr0; b1[i] -= dr1; }
            ht0 = ht0n; ht1 = ht1n; hr0 = hr0n; hr1 = hr1n;
        } else {
            // fgw = sum G * cost_new = sum G*b_old - Δt*z - Δr*s  (per column)
            fgw = (gb0 - (ht0n - ht0) * z0 - (hr0n - hr0) * s0)
                + (gb1 - (ht1n - ht1) * z1 - (hr1n - hr1) * s1);
        }
    }

    fgw += __shfl_xor_sync(FULLMASK, fgw, 1);
    fgw += __shfl_xor_sync(FULLMASK, fgw, 2);
    if (cl == 0)
        out[(node_base + nl) * TT + t] = fgw * SCALEBACK;
}

extern "C" void kernel_launch(void* const* d_in, const int* in_sizes, int n_in,
                              void* d_out, int out_size) {
    (void)in_sizes; (void)n_in; (void)out_size;
    const float* x  = (const float*)d_in[0];
    const int*   ei = (const int*)d_in[1];
    const float* tf = (const float*)d_in[2];
    const float* tm = (const float*)d_in[3];
    float* out = (float*)d_out;

    const int smem_bytes = (8192 + 4352 + 1024 + 128 + 68) * 4;  // 55056 B
    cudaFuncSetAttribute(ltfgw_kernel,
                         cudaFuncAttributeMaxDynamicSharedMemorySize, smem_bytes);
    ltfgw_kernel<<<NND / NODES_PER_BLK, THREADS, smem_bytes>>>(
        x, ei + NND * DEG /* dst row */, tf, tm, out);
}

// round 2
// speedup vs baseline: 1.8169x; 1.8169x over previous
#include <cuda_runtime.h>

#define FULLMASK 0xffffffffu

constexpr int NND = 20000;
constexpr int DEG = 16;
constexpr int NQ  = 17;    // ego-graph size n = DEG+1
constexpr int TT  = 16;    // templates
constexpr int MM  = 8;     // template nodes
constexpr int DD  = 64;    // feature dim
constexpr int NODES_PER_BLK = 4;
constexpr int THREADS = 256;

// Work in base-2 units scaled by 1/EPS:  b = cost * log2(e)/EPS
constexpr float SIG       = 14.4269504088896340f;   // log2(e)/0.1
constexpr float LOGP2     = -4.0874628412503390f;   // log2(1/17)
constexpr float LOGQ2     = -3.0f;                  // log2(1/8)
constexpr float SCALEBACK = 0.0693147180559945f;    // EPS*ln(2)

__device__ __forceinline__ float ex2f_(float x) {
    float y; asm("ex2.approx.ftz.f32 %0, %1;" : "=f"(y) : "f"(x)); return y;
}
__device__ __forceinline__ float lg2f_(float x) {
    float y; asm("lg2.approx.f32 %0, %1;" : "=f"(y) : "f"(x)); return y;
}
__device__ __forceinline__ float rcpf_(float x) {
    float y; asm("rcp.approx.ftz.f32 %0, %1;" : "=f"(y) : "f"(x)); return y;
}

// dynamic smem layout (floats):
//  [0, 8192)       tfT  : transposed template features [d][t*8+j]
//  [+4352)         floc : gathered ego features [4 nodes][17][64]
//  [+1152)         c2s  : template structure [16*8][9]  (stride 9: conflict-free)
//  [+128)          wcol : per-column constant 0.5*(|tf|^2 + b)
//  [+68)           rrow : per-row constant 0.5*(|x|^2 + a)
__global__ __launch_bounds__(THREADS, 2)
void ltfgw_kernel(const float* __restrict__ x,
                  const int*   __restrict__ edge_dst,
                  const float* __restrict__ tf,
                  const float* __restrict__ tm,
                  float*       __restrict__ out)
{
    extern __shared__ float sm[];
    float* tfT  = sm;                    // 8192
    float* floc = sm + 8192;             // 4352
    float* c2s  = sm + 8192 + 4352;      // 1152 (stride 9)
    float* wcol = c2s + 1152;            // 128
    float* rrow = wcol + 128;            // 68

    const int tid = threadIdx.x;
    const int node_base = blockIdx.x * NODES_PER_BLK;

    // ---- stage templates (transposed) ----
    for (int e = tid; e < TT * MM * DD; e += THREADS) {
        int d  = e & 63;
        int tj = e >> 6;                 // t*8 + j
        tfT[d * 128 + tj] = tf[e];
    }
    for (int e = tid; e < TT * MM * MM; e += THREADS)
        c2s[(e >> 3) * 9 + (e & 7)] = tm[e];

    // ---- gather ego features: row 0 = node, rows 1..16 = neighbors ----
    for (int li = tid; li < NODES_PER_BLK * NQ * (DD / 4); li += THREADS) {
        int row = li >> 4;
        int q   = li & 15;
        int nl  = row / NQ;
        int i   = row - nl * NQ;
        int node = node_base + nl;
        int g = (i == 0) ? node : edge_dst[node * DEG + (i - 1)];
        reinterpret_cast<float4*>(floc)[row * 16 + q] =
            reinterpret_cast<const float4*>(x)[g * 16 + q];
    }
    __syncthreads();

    // ---- per-column constants: w = 0.5*(|tf_tj|^2 + (1/8)*sum_k C2[t,j,k]^2) ----
    if (tid < 128) {
        float sq = 0.f;
        #pragma unroll 8
        for (int d = 0; d < DD; d++) { float v = tfT[d * 128 + tid]; sq += v * v; }
        float bb = 0.f;
        #pragma unroll
        for (int k = 0; k < MM; k++) { float c = c2s[tid * 9 + k]; bb += c * c; }
        wcol[tid] = 0.5f * (sq + 0.125f * bb);
    } else if (tid < 128 + NODES_PER_BLK * NQ) {
        // per-row constants: r = 0.5*(|x_i|^2 + a_i), a_0 = 16/17, a_i = 1/17
        int rid = tid - 128;
        float sq = 0.f;
        #pragma unroll 8
        for (int d = 0; d < DD; d++) {
            float v = floc[rid * 64 + ((d + rid) & 63)];   // rotated: bank-conflict-free
            sq += v * v;
        }
        float a = ((rid % NQ) == 0) ? (16.f / 17.f) : (1.f / 17.f);
        rrow[rid] = 0.5f * (sq + a);
    }
    __syncthreads();

    // ---- lane mapping: 4 lanes per (node,template) pair, 2 columns per lane ----
    const int w    = tid >> 5, lane = tid & 31;
    const int nl   = w >> 1;
    const int grp  = lane >> 2, cl = lane & 3;
    const int t    = (w & 1) * 8 + grp;
    const int j0   = cl * 2;
    const int col0 = t * 8 + j0;

    // ---- feature cost (dot products), register-blocked over rows ----
    float b0[NQ], b1[NQ];
    #pragma unroll
    for (int i = 0; i < NQ; i++) { b0[i] = 0.f; b1[i] = 0.f; }

    const float* fl = floc + nl * NQ * DD;
    #pragma unroll 2
    for (int d4 = 0; d4 < DD; d4 += 4) {
        float2 t0 = *reinterpret_cast<const float2*>(&tfT[(d4 + 0) * 128 + col0]);
        float2 t1 = *reinterpret_cast<const float2*>(&tfT[(d4 + 1) * 128 + col0]);
        float2 t2 = *reinterpret_cast<const float2*>(&tfT[(d4 + 2) * 128 + col0]);
        float2 t3 = *reinterpret_cast<const float2*>(&tfT[(d4 + 3) * 128 + col0]);
        #pragma unroll
        for (int i = 0; i < NQ; i++) {
            float4 f4 = *reinterpret_cast<const float4*>(&fl[i * DD + d4]);  // broadcast
            b0[i] += f4.x * t0.x + f4.y * t1.x + f4.z * t2.x + f4.w * t3.x;
            b1[i] += f4.x * t0.y + f4.y * t1.y + f4.z * t2.y + f4.w * t3.y;
        }
    }
    // b = (r_i + w_j - dot) * SIG  == 0.5*(Mcost + constC)/EPS * log2(e)
    {
        const float w0c = wcol[col0], w1c = wcol[col0 + 1];
        #pragma unroll
        for (int i = 0; i < NQ; i++) {
            float r = rrow[nl * NQ + i];
            b0[i] = (r + w0c - b0[i]) * SIG;
            b1[i] = (r + w1c - b1[i]) * SIG;
        }
    }

    // initial H from uniform plan G = 1/136:  s_k = 16/136, z_k = 1/136
    float ht0, hr0, ht1, hr1;
    {
        float cs0 = 0.f, cs1 = 0.f;
        const float* c2r0 = &c2s[col0 * 9];
        const float* c2r1 = &c2s[(col0 + 1) * 9];
        #pragma unroll
        for (int k = 0; k < MM; k++) { cs0 += c2r0[k]; cs1 += c2r1[k]; }
        ht0 = SIG * (16.f / 136.f) * cs0; hr0 = SIG * (1.f / 136.f) * cs0;
        ht1 = SIG * (16.f / 136.f) * cs1; hr1 = SIG * (1.f / 136.f) * cs1;
        b0[0] -= ht0; b1[0] -= ht1;
        #pragma unroll
        for (int i = 1; i < NQ; i++) { b0[i] -= hr0; b1[i] -= hr1; }
    }

    float F[NQ];          // log phase: f potentials; scaled phase: t_i = rcp(rowsum)
    float K0[NQ], K1[NQ]; // kernel matrix exp2(Fhat + Ghat - b)
    float G0 = 0.f, G1 = 0.f;

    // ---- outer 0: two log-domain warmup iterations (numerically safe anchor) ----
    #pragma unroll 1
    for (int it = 0; it < 2; it++) {
        #pragma unroll
        for (int i = 0; i < NQ; i++) {
            float v0l = G0 - b0[i];
            float v1l = G1 - b1[i];
            float mx = fmaxf(v0l, v1l);
            mx = fmaxf(mx, __shfl_xor_sync(FULLMASK, mx, 1));
            mx = fmaxf(mx, __shfl_xor_sync(FULLMASK, mx, 2));
            float s = ex2f_(v0l - mx) + ex2f_(v1l - mx);
            s += __shfl_xor_sync(FULLMASK, s, 1);
            s += __shfl_xor_sync(FULLMASK, s, 2);
            F[i] = LOGP2 - (lg2f_(s) + mx);
        }
        float m0 = F[0] - b0[0], m1 = F[0] - b1[0];
        #pragma unroll
        for (int i = 1; i < NQ; i++) {
            m0 = fmaxf(m0, F[i] - b0[i]);
            m1 = fmaxf(m1, F[i] - b1[i]);
        }
        float s0l = 0.f, s1l = 0.f;
        #pragma unroll
        for (int i = 0; i < NQ; i++) {
            s0l += ex2f_(F[i] - b0[i] - m0);
            s1l += ex2f_(F[i] - b1[i] - m1);
        }
        G0 = LOGQ2 - (lg2f_(s0l) + m0);
        G1 = LOGQ2 - (lg2f_(s1l) + m1);
    }

    // ---- build anchored kernel K = exp2(F + G - b); track w = exp2(-Ghat) ----
    float v0 = 1.f, v1 = 1.f;                 // v = exp2(g - Ghat); g == Ghat now
    float wv0 = ex2f_(-G0), wv1 = ex2f_(-G1); // cold-start v for future outers
    #pragma unroll
    for (int i = 0; i < NQ; i++) {
        K0[i] = ex2f_(F[i] + G0 - b0[i]);
        K1[i] = ex2f_(F[i] + G1 - b1[i]);
    }

    float fgw = 0.f;
    const float p17 = 1.f / 17.f;

    #pragma unroll 1
    for (int outer = 0; outer < 4; outer++) {
        const int nit = outer ? 10 : 8;       // outer 0 already did 2 log iters
        #pragma unroll 1
        for (int it = 0; it < nit; it++) {
            float cs0 = 0.f, cs1 = 0.f;
            #pragma unroll
            for (int i = 0; i < NQ; i++) {
                float rs = fmaf(K0[i], v0, K1[i] * v1);
                rs += __shfl_xor_sync(FULLMASK, rs, 1);
                rs += __shfl_xor_sync(FULLMASK, rs, 2);
                float ti = rcpf_(rs);         // u_i = (1/17) * ti
                F[i] = ti;
                cs0 = fmaf(K0[i], ti, cs0);
                cs1 = fmaf(K1[i], ti, cs1);
            }
            v0 = 2.125f * rcpf_(cs0);         // (17/8) * rcp
            v1 = 2.125f * rcpf_(cs1);
        }

        // ---- plan marginals z (row 0), s (rows 1..16), and sum(P*b) ----
        float vp0 = v0 * p17, vp1 = v1 * p17;
        float z0 = F[0] * K0[0] * vp0;
        float z1 = F[0] * K1[0] * vp1;
        float gb0 = z0 * b0[0], gb1 = z1 * b1[0];
        float s0 = 0.f, s1 = 0.f;
        #pragma unroll
        for (int i = 1; i < NQ; i++) {
            float a0 = F[i] * K0[i] * vp0;
            float a1 = F[i] * K1[i] * vp1;
            s0 += a0; s1 += a1;
            gb0 = fmaf(a0, b0[i], gb0);
            gb1 = fmaf(a1, b1[i], gb1);
        }

        // assemble full s[8], z[8] across the 4-lane group
        float sf[MM], zf[MM];
        const int lb = lane & ~3;
        #pragma unroll
        for (int kk = 0; kk < 4; kk++) {
            sf[2 * kk]     = __shfl_sync(FULLMASK, s0, lb + kk);
            sf[2 * kk + 1] = __shfl_sync(FULLMASK, s1, lb + kk);
            zf[2 * kk]     = __shfl_sync(FULLMASK, z0, lb + kk);
            zf[2 * kk + 1] = __shfl_sync(FULLMASK, z1, lb + kk);
        }
        // new H = (C1 G C2): row0 uses s.C2, rows>=1 use z.C2
        float ht0n = 0.f, hr0n = 0.f, ht1n = 0.f, hr1n = 0.f;
        {
            const float* c2r0 = &c2s[col0 * 9];
            const float* c2r1 = &c2s[(col0 + 1) * 9];
            #pragma unroll
            for (int k = 0; k < MM; k++) {
                float ca = c2r0[k], cb = c2r1[k];
                ht0n = fmaf(sf[k], ca, ht0n); hr0n = fmaf(zf[k], ca, hr0n);
                ht1n = fmaf(sf[k], cb, ht1n); hr1n = fmaf(zf[k], cb, hr1n);
            }
        }
        ht0n *= SIG; hr0n *= SIG; ht1n *= SIG; hr1n *= SIG;
        float dt0 = ht0n - ht0, dt1 = ht1n - ht1;
        float dr0 = hr0n - hr0, dr1 = hr1n - hr1;

        if (outer < 3) {
            // fold Δh into cost: b_new = b_old - Δh
            b0[0] -= dt0; b1[0] -= dt1;
            #pragma unroll
            for (int i = 1; i < NQ; i++) { b0[i] -= dr0; b1[i] -= dr1; }
            ht0 = ht0n; ht1 = ht1n; hr0 = hr0n; hr1 = hr1n;

            // rescale kernel to new anchors: K' = K * u_i * v_j * exp2(Δh)
            float et0 = ex2f_(dt0), et1 = ex2f_(dt1);
            float er0 = ex2f_(dr0), er1 = ex2f_(dr1);
            float m00 = vp0 * et0, m01 = vp1 * et1;   // row 0 factors
            float mr0 = vp0 * er0, mr1 = vp1 * er1;   // rows 1..16 factors
            K0[0] *= F[0] * m00; K1[0] *= F[0] * m01;
            #pragma unroll
            for (int i = 1; i < NQ; i++) {
                float ti = F[i];
                K0[i] *= ti * mr0;
                K1[i] *= ti * mr1;
            }
            // cold-start v for next outer: exp2(-Ghat_new) = w / v_final
            wv0 *= rcpf_(v0); wv1 *= rcpf_(v1);
            v0 = wv0; v1 = wv1;
        } else {
            // fgw = sum P * b_final = sum(P*b) - Δt*z - Δr*s   (per column)
            fgw = (gb0 - dt0 * z0 - dr0 * s0)
                + (gb1 - dt1 * z1 - dr1 * s1);
        }
    }

    fgw += __shfl_xor_sync(FULLMASK, fgw, 1);
    fgw += __shfl_xor_sync(FULLMASK, fgw, 2);
    if (cl == 0)
        out[(node_base + nl) * TT + t] = fgw * SCALEBACK;
}

extern "C" void kernel_launch(void* const* d_in, const int* in_sizes, int n_in,
                              void* d_out, int out_size) {
    (void)in_sizes; (void)n_in; (void)out_size;
    const float* x  = (const float*)d_in[0];
    const int*   ei = (const int*)d_in[1];
    const float* tf = (const float*)d_in[2];
    const float* tm = (const float*)d_in[3];
    float* out = (float*)d_out;

    const int smem_bytes = (8192 + 4352 + 1152 + 128 + 68) * 4;  // 55568 B
    cudaFuncSetAttribute(ltfgw_kernel,
                         cudaFuncAttributeMaxDynamicSharedMemorySize, smem_bytes);
    ltfgw_kernel<<<NND / NODES_PER_BLK, THREADS, smem_bytes>>>(
        x, ei + NND * DEG /* dst row */, tf, tm, out);
}

// round 3
// speedup vs baseline: 1.8185x; 1.0009x over previous
#include <cuda_runtime.h>

#define FULLMASK 0xffffffffu

constexpr int NND = 20000;
constexpr int DEG = 16;
constexpr int NQ  = 17;    // ego-graph size n = DEG+1
constexpr int TT  = 16;    // templates
constexpr int MM  = 8;     // template nodes
constexpr int DD  = 64;    // feature dim
constexpr int NODES_PER_BLK = 4;
constexpr int THREADS = 256;

// Work in base-2 units scaled by 1/EPS:  b = cost * log2(e)/EPS
constexpr float SIG       = 14.4269504088896340f;   // log2(e)/0.1
constexpr float LOGP2     = -4.0874628412503390f;   // log2(1/17)
constexpr float LOGQ2     = -3.0f;                  // log2(1/8)
constexpr float SCALEBACK = 0.0693147180559945f;    // EPS*ln(2)

__device__ __forceinline__ float ex2f_(float x) {
    float y; asm("ex2.approx.ftz.f32 %0, %1;" : "=f"(y) : "f"(x)); return y;
}
__device__ __forceinline__ float lg2f_(float x) {
    float y; asm("lg2.approx.f32 %0, %1;" : "=f"(y) : "f"(x)); return y;
}
__device__ __forceinline__ float rcpf_(float x) {
    float y; asm("rcp.approx.ftz.f32 %0, %1;" : "=f"(y) : "f"(x)); return y;
}

// dynamic smem layout (floats):
//  [0, 8192)       tfT  : transposed template features [d][t*8+j]
//  [+4352)         floc : gathered ego features [4 nodes][17][64]
//  [+1152)         c2s  : template structure [16*8][9]  (stride 9: conflict-free)
//  [+128)          wcol : per-column constant 0.5*(|tf|^2 + b)
//  [+68)           rrow : per-row constant 0.5*(|x|^2 + a)
__global__ __launch_bounds__(THREADS, 2)
void ltfgw_kernel(const float* __restrict__ x,
                  const int*   __restrict__ edge_dst,
                  const float* __restrict__ tf,
                  const float* __restrict__ tm,
                  float*       __restrict__ out)
{
    extern __shared__ float sm[];
    float* tfT  = sm;                    // 8192
    float* floc = sm + 8192;             // 4352
    float* c2s  = sm + 8192 + 4352;      // 1152 (stride 9)
    float* wcol = c2s + 1152;            // 128
    float* rrow = wcol + 128;            // 68

    const int tid = threadIdx.x;
    const int node_base = blockIdx.x * NODES_PER_BLK;

    // ---- stage templates (transposed) ----
    for (int e = tid; e < TT * MM * DD; e += THREADS) {
        int d  = e & 63;
        int tj = e >> 6;                 // t*8 + j
        tfT[d * 128 + tj] = tf[e];
    }
    for (int e = tid; e < TT * MM * MM; e += THREADS)
        c2s[(e >> 3) * 9 + (e & 7)] = tm[e];

    // ---- gather ego features: row 0 = node, rows 1..16 = neighbors ----
    for (int li = tid; li < NODES_PER_BLK * NQ * (DD / 4); li += THREADS) {
        int row = li >> 4;
        int q   = li & 15;
        int nl  = row / NQ;
        int i   = row - nl * NQ;
        int node = node_base + nl;
        int g = (i == 0) ? node : edge_dst[node * DEG + (i - 1)];
        reinterpret_cast<float4*>(floc)[row * 16 + q] =
            reinterpret_cast<const float4*>(x)[g * 16 + q];
    }
    __syncthreads();

    // ---- per-column constants: w = 0.5*(|tf_tj|^2 + (1/8)*sum_k C2[t,j,k]^2) ----
    if (tid < 128) {
        float sq = 0.f;
        #pragma unroll 8
        for (int d = 0; d < DD; d++) { float v = tfT[d * 128 + tid]; sq += v * v; }
        float bb = 0.f;
        #pragma unroll
        for (int k = 0; k < MM; k++) { float c = c2s[tid * 9 + k]; bb += c * c; }
        wcol[tid] = 0.5f * (sq + 0.125f * bb);
    } else if (tid < 128 + NODES_PER_BLK * NQ) {
        // per-row constants: r = 0.5*(|x_i|^2 + a_i), a_0 = 16/17, a_i = 1/17
        int rid = tid - 128;
        float sq = 0.f;
        #pragma unroll 8
        for (int d = 0; d < DD; d++) {
            float v = floc[rid * 64 + ((d + rid) & 63)];   // rotated: bank-conflict-free
            sq += v * v;
        }
        float a = ((rid % NQ) == 0) ? (16.f / 17.f) : (1.f / 17.f);
        rrow[rid] = 0.5f * (sq + a);
    }
    __syncthreads();

    // ---- lane mapping: 4 lanes per (node,template) pair, 2 columns per lane ----
    const int w    = tid >> 5, lane = tid & 31;
    const int nl   = w >> 1;
    const int grp  = lane >> 2, cl = lane & 3;
    const int t    = (w & 1) * 8 + grp;
    const int j0   = cl * 2;
    const int col0 = t * 8 + j0;

    // ---- feature cost (dot products), register-blocked over rows ----
    float b0[NQ], b1[NQ];
    #pragma unroll
    for (int i = 0; i < NQ; i++) { b0[i] = 0.f; b1[i] = 0.f; }

    const float* fl = floc + nl * NQ * DD;
    #pragma unroll 2
    for (int d4 = 0; d4 < DD; d4 += 4) {
        float2 t0 = *reinterpret_cast<const float2*>(&tfT[(d4 + 0) * 128 + col0]);
        float2 t1 = *reinterpret_cast<const float2*>(&tfT[(d4 + 1) * 128 + col0]);
        float2 t2 = *reinterpret_cast<const float2*>(&tfT[(d4 + 2) * 128 + col0]);
        float2 t3 = *reinterpret_cast<const float2*>(&tfT[(d4 + 3) * 128 + col0]);
        #pragma unroll
        for (int i = 0; i < NQ; i++) {
            float4 f4 = *reinterpret_cast<const float4*>(&fl[i * DD + d4]);  // broadcast
            b0[i] += f4.x * t0.x + f4.y * t1.x + f4.z * t2.x + f4.w * t3.x;
            b1[i] += f4.x * t0.y + f4.y * t1.y + f4.z * t2.y + f4.w * t3.y;
        }
    }
    // b = (r_i + w_j - dot) * SIG  == 0.5*(Mcost + constC)/EPS * log2(e)
    {
        const float w0c = wcol[col0], w1c = wcol[col0 + 1];
        #pragma unroll
        for (int i = 0; i < NQ; i++) {
            float r = rrow[nl * NQ + i];
            b0[i] = (r + w0c - b0[i]) * SIG;
            b1[i] = (r + w1c - b1[i]) * SIG;
        }
    }

    // initial H from uniform plan G = 1/136:  s_k = 16/136, z_k = 1/136
    float ht0, hr0, ht1, hr1;
    {
        float cs0 = 0.f, cs1 = 0.f;
        const float* c2r0 = &c2s[col0 * 9];
        const float* c2r1 = &c2s[(col0 + 1) * 9];
        #pragma unroll
        for (int k = 0; k < MM; k++) { cs0 += c2r0[k]; cs1 += c2r1[k]; }
        ht0 = SIG * (16.f / 136.f) * cs0; hr0 = SIG * (1.f / 136.f) * cs0;
        ht1 = SIG * (16.f / 136.f) * cs1; hr1 = SIG * (1.f / 136.f) * cs1;
        b0[0] -= ht0; b1[0] -= ht1;
        #pragma unroll
        for (int i = 1; i < NQ; i++) { b0[i] -= hr0; b1[i] -= hr1; }
    }

    float F[NQ];          // log phase: f potentials; scaled phase: t_i = rcp(rowsum)
    float K0[NQ], K1[NQ]; // kernel matrix exp2(Fhat + Ghat - b)
    float G0 = 0.f, G1 = 0.f;

    // ---- outer 0: two log-domain warmup iterations (numerically safe anchor) ----
    #pragma unroll 1
    for (int it = 0; it < 2; it++) {
        #pragma unroll
        for (int i = 0; i < NQ; i++) {
            float v0l = G0 - b0[i];
            float v1l = G1 - b1[i];
            float mx = fmaxf(v0l, v1l);
            mx = fmaxf(mx, __shfl_xor_sync(FULLMASK, mx, 1));
            mx = fmaxf(mx, __shfl_xor_sync(FULLMASK, mx, 2));
            float s = ex2f_(v0l - mx) + ex2f_(v1l - mx);
            s += __shfl_xor_sync(FULLMASK, s, 1);
            s += __shfl_xor_sync(FULLMASK, s, 2);
            F[i] = LOGP2 - (lg2f_(s) + mx);
        }
        float m0 = F[0] - b0[0], m1 = F[0] - b1[0];
        #pragma unroll
        for (int i = 1; i < NQ; i++) {
            m0 = fmaxf(m0, F[i] - b0[i]);
            m1 = fmaxf(m1, F[i] - b1[i]);
        }
        float s0l = 0.f, s1l = 0.f;
        #pragma unroll
        for (int i = 0; i < NQ; i++) {
            s0l += ex2f_(F[i] - b0[i] - m0);
            s1l += ex2f_(F[i] - b1[i] - m1);
        }
        G0 = LOGQ2 - (lg2f_(s0l) + m0);
        G1 = LOGQ2 - (lg2f_(s1l) + m1);
    }

    // ---- build anchored kernel K = exp2(F + G - b); track w = exp2(-Ghat) ----
    float v0 = 1.f, v1 = 1.f;                 // v = exp2(g - Ghat); g == Ghat now
    float wv0 = ex2f_(-G0), wv1 = ex2f_(-G1); // cold-start v for future outers
    #pragma unroll
    for (int i = 0; i < NQ; i++) {
        K0[i] = ex2f_(F[i] + G0 - b0[i]);
        K1[i] = ex2f_(F[i] + G1 - b1[i]);
    }

    float fgw = 0.f;
    const float p17 = 1.f / 17.f;

    #pragma unroll 1
    for (int outer = 0; outer < 4; outer++) {
        const int nit = outer ? 10 : 8;       // outer 0 already did 2 log iters
        #pragma unroll 1
        for (int it = 0; it < nit; it++) {
            float cs0 = 0.f, cs1 = 0.f;
            #pragma unroll
            for (int i = 0; i < NQ; i++) {
                float rs = fmaf(K0[i], v0, K1[i] * v1);
                rs += __shfl_xor_sync(FULLMASK, rs, 1);
                rs += __shfl_xor_sync(FULLMASK, rs, 2);
                float ti = rcpf_(rs);         // u_i = (1/17) * ti
                F[i] = ti;
                cs0 = fmaf(K0[i], ti, cs0);
                cs1 = fmaf(K1[i], ti, cs1);
            }
            v0 = 2.125f * rcpf_(cs0);         // (17/8) * rcp
            v1 = 2.125f * rcpf_(cs1);
        }

        // ---- plan marginals z (row 0), s (rows 1..16), and sum(P*b) ----
        float vp0 = v0 * p17, vp1 = v1 * p17;
        float z0 = F[0] * K0[0] * vp0;
        float z1 = F[0] * K1[0] * vp1;
        float gb0 = z0 * b0[0], gb1 = z1 * b1[0];
        float s0 = 0.f, s1 = 0.f;
        #pragma unroll
        for (int i = 1; i < NQ; i++) {
            float a0 = F[i] * K0[i] * vp0;
            float a1 = F[i] * K1[i] * vp1;
            s0 += a0; s1 += a1;
            gb0 = fmaf(a0, b0[i], gb0);
            gb1 = fmaf(a1, b1[i], gb1);
        }

        // assemble full s[8], z[8] across the 4-lane group
        float sf[MM], zf[MM];
        const int lb = lane & ~3;
        #pragma unroll
        for (int kk = 0; kk < 4; kk++) {
            sf[2 * kk]     = __shfl_sync(FULLMASK, s0, lb + kk);
            sf[2 * kk + 1] = __shfl_sync(FULLMASK, s1, lb + kk);
            zf[2 * kk]     = __shfl_sync(FULLMASK, z0, lb + kk);
            zf[2 * kk + 1] = __shfl_sync(FULLMASK, z1, lb + kk);
        }
        // new H = (C1 G C2): row0 uses s.C2, rows>=1 use z.C2
        float ht0n = 0.f, hr0n = 0.f, ht1n = 0.f, hr1n = 0.f;
        {
            const float* c2r0 = &c2s[col0 * 9];
            const float* c2r1 = &c2s[(col0 + 1) * 9];
            #pragma unroll
            for (int k = 0; k < MM; k++) {
                float ca = c2r0[k], cb = c2r1[k];
                ht0n = fmaf(sf[k], ca, ht0n); hr0n = fmaf(zf[k], ca, hr0n);
                ht1n = fmaf(sf[k], cb, ht1n); hr1n = fmaf(zf[k], cb, hr1n);
            }
        }
        ht0n *= SIG; hr0n *= SIG; ht1n *= SIG; hr1n *= SIG;
        float dt0 = ht0n - ht0, dt1 = ht1n - ht1;
        float dr0 = hr0n - hr0, dr1 = hr1n - hr1;

        if (outer < 3) {
            // fold Δh into cost: b_new = b_old - Δh
            b0[0] -= dt0; b1[0] -= dt1;
            #pragma unroll
            for (int i = 1; i < NQ; i++) { b0[i] -= dr0; b1[i] -= dr1; }
            ht0 = ht0n; ht1 = ht1n; hr0 = hr0n; hr1 = hr1n;

            // rescale kernel to new anchors: K' = K * u_i * v_j * exp2(Δh)
            float et0 = ex2f_(dt0), et1 = ex2f_(dt1);
            float er0 = ex2f_(dr0), er1 = ex2f_(dr1);
            float m00 = vp0 * et0, m01 = vp1 * et1;   // row 0 factors
            float mr0 = vp0 * er0, mr1 = vp1 * er1;   // rows 1..16 factors
            K0[0] *= F[0] * m00; K1[0] *= F[0] * m01;
            #pragma unroll
            for (int i = 1; i < NQ; i++) {
                float ti = F[i];
                K0[i] *= ti * mr0;
                K1[i] *= ti * mr1;
            }
            // cold-start v for next outer: exp2(-Ghat_new) = w / v_final
            wv0 *= rcpf_(v0); wv1 *= rcpf_(v1);
            v0 = wv0; v1 = wv1;
        } else {
            // fgw = sum P * b_final = sum(P*b) - Δt*z - Δr*s   (per column)
            fgw = (gb0 - dt0 * z0 - dr0 * s0)
                + (gb1 - dt1 * z1 - dr1 * s1);
        }
    }

    fgw += __shfl_xor_sync(FULLMASK, fgw, 1);
    fgw += __shfl_xor_sync(FULLMASK, fgw, 2);
    if (cl == 0)
        out[(node_base + nl) * TT + t] = fgw * SCALEBACK;
}

extern "C" void kernel_launch(void* const* d_in, const int* in_sizes, int n_in,
                              void* d_out, int out_size) {
    (void)in_sizes; (void)n_in; (void)out_size;
    const float* x  = (const float*)d_in[0];
    const int*   ei = (const int*)d_in[1];
    const float* tf = (const float*)d_in[2];
    const float* tm = (const float*)d_in[3];
    float* out = (float*)d_out;

    const int smem_bytes = (8192 + 4352 + 1152 + 128 + 68) * 4;  // 55568 B
    cudaFuncSetAttribute(ltfgw_kernel,
                         cudaFuncAttributeMaxDynamicSharedMemorySize, smem_bytes);
    ltfgw_kernel<<<NND / NODES_PER_BLK, THREADS, smem_bytes>>>(
        x, ei + NND * DEG /* dst row */, tf, tm, out);
}